// round 1
// baseline (speedup 1.0000x reference)
#include <cuda_runtime.h>

#define SEQ  2048
#define EMB  1024
#define NH   16
#define HD   64
#define BATCH 4

// Scratch (no cudaMalloc allowed): Q,K,V in [B,H,S,HD], O in [B,S,E]
__device__ float g_Q[BATCH*NH*SEQ*HD];
__device__ float g_K[BATCH*NH*SEQ*HD];
__device__ float g_V[BATCH*NH*SEQ*HD];
__device__ float g_O[BATCH*SEQ*EMB];

// ---------------------------------------------------------------------------
// Fused QKV projection: y = x @ W^T, written straight into [B,H,S,HD] layout.
// Both x and W are row-major with K contiguous -> NT GEMM.
// Tiles: BM=BN=64, BK=16. 256 threads, 4x4 micro-tile each.
// grid = (N/64=16, M/64=128, 3); block col by == head index (BN==HD==64).
// ---------------------------------------------------------------------------
__global__ __launch_bounds__(256, 1)
void qkv_gemm(const float* __restrict__ x,
              const float* __restrict__ Wq,
              const float* __restrict__ Wk,
              const float* __restrict__ Wv)
{
    const float* W;
    float* Out;
    if (blockIdx.z == 0)      { W = Wq; Out = g_Q; }
    else if (blockIdx.z == 1) { W = Wk; Out = g_K; }
    else                      { W = Wv; Out = g_V; }

    __shared__ float As[16][68];   // [BK][BM+pad], pad keeps float4 alignment
    __shared__ float Bs[16][68];

    const int t  = threadIdx.x;
    const int lr = t >> 2;         // load row 0..63
    const int lq = t & 3;          // load quarter (which float4 along K)
    const int bx = blockIdx.y;     // M block
    const int by = blockIdx.x;     // N block == head

    const float4* Ag = reinterpret_cast<const float4*>(x + (size_t)(bx*64 + lr)*EMB) + lq;
    const float4* Bg = reinterpret_cast<const float4*>(W + (size_t)(by*64 + lr)*EMB) + lq;

    float acc[4][4] = {};
    const int ty = t >> 4, tx = t & 15;

    for (int k0 = 0; k0 < EMB/16; k0++) {
        float4 av = Ag[k0*4];
        float4 bv = Bg[k0*4];
        As[lq*4+0][lr] = av.x; As[lq*4+1][lr] = av.y;
        As[lq*4+2][lr] = av.z; As[lq*4+3][lr] = av.w;
        Bs[lq*4+0][lr] = bv.x; Bs[lq*4+1][lr] = bv.y;
        Bs[lq*4+2][lr] = bv.z; Bs[lq*4+3][lr] = bv.w;
        __syncthreads();
#pragma unroll
        for (int kk = 0; kk < 16; kk++) {
            float4 a4 = reinterpret_cast<const float4*>(&As[kk][0])[ty];
            float4 b4 = reinterpret_cast<const float4*>(&Bs[kk][0])[tx];
            float a[4] = {a4.x, a4.y, a4.z, a4.w};
            float b[4] = {b4.x, b4.y, b4.z, b4.w};
#pragma unroll
            for (int i = 0; i < 4; i++)
#pragma unroll
                for (int j = 0; j < 4; j++)
                    acc[i][j] += a[i]*b[j];
        }
        __syncthreads();
    }

    // n = by*64 + tx*4 + j  ->  head h = by, dim d = tx*4 + j (contiguous float4)
#pragma unroll
    for (int i = 0; i < 4; i++) {
        int m = bx*64 + ty*4 + i;
        int b = m >> 11, s = m & 2047;
        float4 v = make_float4(acc[i][0], acc[i][1], acc[i][2], acc[i][3]);
        *reinterpret_cast<float4*>(Out + (((size_t)(b*NH + by)*SEQ + s)*HD + tx*4)) = v;
    }
}

// ---------------------------------------------------------------------------
// Causal flash attention, fp32. One block = 64 query rows of one (b,h).
// 256 threads: thread t -> query row r=t/4, quarter q=t&3 (owns 16 score cols,
// accumulates full 64-dim O partial over its columns; shfl-reduced at the end).
// Only key blocks kb <= qb are visited (causal).
// ---------------------------------------------------------------------------
__global__ __launch_bounds__(256, 1)
void attn_kernel()
{
    __shared__ float Ks[64][68];
    __shared__ float Vs[64][68];

    const int t  = threadIdx.x;
    const int qb = blockIdx.x, h = blockIdx.y, b = blockIdx.z;
    const int r  = t >> 2;     // query row in tile
    const int qq = t & 3;      // column quarter

    const float* Qb = g_Q + ((size_t)(b*NH + h)*SEQ + qb*64)*HD;
    const float* Kb = g_K + ((size_t)(b*NH + h)*SEQ)*HD;
    const float* Vb = g_V + ((size_t)(b*NH + h)*SEQ)*HD;

    // Stage Q tile through smem, then pull own row to registers
#pragma unroll
    for (int u = 0; u < 4; u++) {
        int li = u*256 + t;
        int row = li >> 4, c4 = li & 15;
        reinterpret_cast<float4*>(&Ks[row][0])[c4] =
            reinterpret_cast<const float4*>(Qb)[li];
    }
    __syncthreads();
    float qreg[64];
#pragma unroll
    for (int d = 0; d < 64; d++) qreg[d] = Ks[r][d];
    __syncthreads();

    float o[64];
#pragma unroll
    for (int d = 0; d < 64; d++) o[d] = 0.f;
    float mrun = -1e30f, l = 0.f;
    const int qrow = qb*64 + r;

    for (int kb = 0; kb <= qb; kb++) {
        // Load K and V tiles (64x64 each)
#pragma unroll
        for (int u = 0; u < 4; u++) {
            int li = u*256 + t;
            int row = li >> 4, c4 = li & 15;
            reinterpret_cast<float4*>(&Ks[row][0])[c4] =
                reinterpret_cast<const float4*>(Kb + (size_t)kb*64*HD)[li];
            reinterpret_cast<float4*>(&Vs[row][0])[c4] =
                reinterpret_cast<const float4*>(Vb + (size_t)kb*64*HD)[li];
        }
        __syncthreads();

        float s[16];
        const bool diag = (kb == qb);
#pragma unroll
        for (int i = 0; i < 16; i++) {
            int c = qq*16 + i;
            const float4* kr = reinterpret_cast<const float4*>(&Ks[c][0]);
            float acc = 0.f;
#pragma unroll
            for (int d4 = 0; d4 < 16; d4++) {
                float4 kv = kr[d4];
                acc += qreg[d4*4+0]*kv.x + qreg[d4*4+1]*kv.y
                     + qreg[d4*4+2]*kv.z + qreg[d4*4+3]*kv.w;
            }
            acc *= 0.125f;                      // 1/sqrt(64)
            if (diag && (kb*64 + c > qrow)) acc = -1e30f;
            s[i] = acc;
        }

        // Row max across 16 local cols + 4 cooperating lanes
        float mt = s[0];
#pragma unroll
        for (int i = 1; i < 16; i++) mt = fmaxf(mt, s[i]);
        mt = fmaxf(mt, __shfl_xor_sync(0xffffffffu, mt, 1));
        mt = fmaxf(mt, __shfl_xor_sync(0xffffffffu, mt, 2));

        float mnew = fmaxf(mrun, mt);
        float corr = __expf(mrun - mnew);
        mrun = mnew;
        l *= corr;
#pragma unroll
        for (int d = 0; d < 64; d++) o[d] *= corr;

#pragma unroll
        for (int i = 0; i < 16; i++) {
            float p = __expf(s[i] - mrun);
            l += p;
            int c = qq*16 + i;
            const float4* vr = reinterpret_cast<const float4*>(&Vs[c][0]);
#pragma unroll
            for (int d4 = 0; d4 < 16; d4++) {
                float4 vv = vr[d4];
                o[d4*4+0] += p*vv.x;
                o[d4*4+1] += p*vv.y;
                o[d4*4+2] += p*vv.z;
                o[d4*4+3] += p*vv.w;
            }
        }
        __syncthreads();
    }

    // Reduce partial O and l across the 4 cooperating lanes
#pragma unroll
    for (int d = 0; d < 64; d++) {
        o[d] += __shfl_xor_sync(0xffffffffu, o[d], 1);
        o[d] += __shfl_xor_sync(0xffffffffu, o[d], 2);
    }
    l += __shfl_xor_sync(0xffffffffu, l, 1);
    l += __shfl_xor_sync(0xffffffffu, l, 2);
    float inv = 1.f / l;

    // Each lane writes its quarter of the output row: O[b, s, h*64 + qq*16 .. +16)
    float* Ob = g_O + ((size_t)b*SEQ + qrow)*EMB + h*HD + qq*16;
#pragma unroll
    for (int j4 = 0; j4 < 4; j4++) {
        float4 v = make_float4(o[qq*16 + j4*4 + 0]*inv, o[qq*16 + j4*4 + 1]*inv,
                               o[qq*16 + j4*4 + 2]*inv, o[qq*16 + j4*4 + 3]*inv);
        reinterpret_cast<float4*>(Ob)[j4] = v;
    }
}

// ---------------------------------------------------------------------------
// Output projection: out = g_O @ Wo^T + bo   (same NT GEMM + bias epilogue)
// ---------------------------------------------------------------------------
__global__ __launch_bounds__(256, 1)
void proj_gemm(const float* __restrict__ Wo,
               const float* __restrict__ bo,
               float* __restrict__ outp)
{
    __shared__ float As[16][68];
    __shared__ float Bs[16][68];

    const int t  = threadIdx.x;
    const int lr = t >> 2, lq = t & 3;
    const int bx = blockIdx.y, by = blockIdx.x;

    const float4* Ag = reinterpret_cast<const float4*>(g_O + (size_t)(bx*64 + lr)*EMB) + lq;
    const float4* Bg = reinterpret_cast<const float4*>(Wo  + (size_t)(by*64 + lr)*EMB) + lq;

    float acc[4][4] = {};
    const int ty = t >> 4, tx = t & 15;

    for (int k0 = 0; k0 < EMB/16; k0++) {
        float4 av = Ag[k0*4];
        float4 bv = Bg[k0*4];
        As[lq*4+0][lr] = av.x; As[lq*4+1][lr] = av.y;
        As[lq*4+2][lr] = av.z; As[lq*4+3][lr] = av.w;
        Bs[lq*4+0][lr] = bv.x; Bs[lq*4+1][lr] = bv.y;
        Bs[lq*4+2][lr] = bv.z; Bs[lq*4+3][lr] = bv.w;
        __syncthreads();
#pragma unroll
        for (int kk = 0; kk < 16; kk++) {
            float4 a4 = reinterpret_cast<const float4*>(&As[kk][0])[ty];
            float4 b4 = reinterpret_cast<const float4*>(&Bs[kk][0])[tx];
            float a[4] = {a4.x, a4.y, a4.z, a4.w};
            float b[4] = {b4.x, b4.y, b4.z, b4.w};
#pragma unroll
            for (int i = 0; i < 4; i++)
#pragma unroll
                for (int j = 0; j < 4; j++)
                    acc[i][j] += a[i]*b[j];
        }
        __syncthreads();
    }

    const int n = by*64 + tx*4;
    float4 bias = *reinterpret_cast<const float4*>(bo + n);
#pragma unroll
    for (int i = 0; i < 4; i++) {
        int m = bx*64 + ty*4 + i;
        float4 v = make_float4(acc[i][0] + bias.x, acc[i][1] + bias.y,
                               acc[i][2] + bias.z, acc[i][3] + bias.w);
        *reinterpret_cast<float4*>(outp + (size_t)m*EMB + n) = v;
    }
}

// ---------------------------------------------------------------------------
extern "C" void kernel_launch(void* const* d_in, const int* in_sizes, int n_in,
                              void* d_out, int out_size)
{
    const float* x  = (const float*)d_in[0];
    const float* Wq = (const float*)d_in[1];
    const float* Wk = (const float*)d_in[2];
    const float* Wv = (const float*)d_in[3];
    const float* Wo = (const float*)d_in[4];
    const float* bo = (const float*)d_in[5];
    float* out = (float*)d_out;

    qkv_gemm<<<dim3(16, 128, 3), 256>>>(x, Wq, Wk, Wv);
    attn_kernel<<<dim3(32, 16, 4), 256>>>();
    proj_gemm<<<dim3(16, 128), 256>>>(Wo, bo, out);
}

// round 2
// speedup vs baseline: 9.1267x; 9.1267x over previous
#include <cuda_runtime.h>
#include <cstdint>

#define SEQ  2048
#define EMB  1024
#define NH   16
#define HD   64
#define BATCH 4

// Scratch (no cudaMalloc allowed)
__device__ float g_Q[BATCH*NH*SEQ*HD];
__device__ float g_K[BATCH*NH*SEQ*HD];
__device__ float g_V[BATCH*NH*SEQ*HD];
__device__ float g_O[BATCH*SEQ*EMB];

__device__ __forceinline__ float to_tf32(float x) {
    float r; asm("cvt.rna.tf32.f32 %0, %1;" : "=f"(r) : "f"(x)); return r;
}

// D += A(16x8,row) * B(8x8,col)  tf32
__device__ __forceinline__ void mma8(float* d, float a0, float a1, float a2, float a3,
                                     float b0, float b1) {
    uint32_t A0=__float_as_uint(a0), A1=__float_as_uint(a1),
             A2=__float_as_uint(a2), A3=__float_as_uint(a3);
    uint32_t B0=__float_as_uint(b0), B1=__float_as_uint(b1);
    asm volatile("mma.sync.aligned.m16n8k8.row.col.f32.tf32.tf32.f32 "
                 "{%0,%1,%2,%3},{%4,%5,%6,%7},{%8,%9},{%0,%1,%2,%3};"
                 : "+f"(d[0]), "+f"(d[1]), "+f"(d[2]), "+f"(d[3])
                 : "r"(A0), "r"(A1), "r"(A2), "r"(A3), "r"(B0), "r"(B1));
}

#define SA 36   // smem row stride (floats): 36 % 32 = 4 -> conflict-free frag loads

// ---------------------------------------------------------------------------
// NT GEMM mainloop: C[128x128] = A[128xK] * B[128xK]^T, tf32 mma.
// 256 threads = 8 warps (2 M x 4 N), warp tile 64x32, BK = 32.
// ---------------------------------------------------------------------------
__device__ __forceinline__ void gemm_mainloop(const float* __restrict__ A,
                                              const float* __restrict__ B,
                                              float* As, float* Bs,
                                              int bm0, int bn0,
                                              float acc[4][4][4]) {
    const int t = threadIdx.x;
    const int warp = t >> 5, lane = t & 31, g = lane >> 2, q4 = lane & 3;
    const int wm = (warp & 1) * 64, wn = (warp >> 1) * 32;

    for (int k0 = 0; k0 < EMB; k0 += 32) {
#pragma unroll
        for (int u = 0; u < 4; u++) {
            int idx = u*256 + t;
            int row = idx >> 3, c4 = idx & 7;
            float4 av = *(const float4*)(A + (size_t)(bm0+row)*EMB + k0 + c4*4);
            float4 bv = *(const float4*)(B + (size_t)(bn0+row)*EMB + k0 + c4*4);
            av.x = to_tf32(av.x); av.y = to_tf32(av.y);
            av.z = to_tf32(av.z); av.w = to_tf32(av.w);
            bv.x = to_tf32(bv.x); bv.y = to_tf32(bv.y);
            bv.z = to_tf32(bv.z); bv.w = to_tf32(bv.w);
            *(float4*)(As + row*SA + c4*4) = av;
            *(float4*)(Bs + row*SA + c4*4) = bv;
        }
        __syncthreads();
#pragma unroll
        for (int ks = 0; ks < 4; ks++) {
            float af[4][4], bf[4][2];
#pragma unroll
            for (int mt = 0; mt < 4; mt++) {
                int r = wm + mt*16 + g;
                af[mt][0] = As[r*SA     + ks*8 + q4];
                af[mt][1] = As[(r+8)*SA + ks*8 + q4];
                af[mt][2] = As[r*SA     + ks*8 + q4 + 4];
                af[mt][3] = As[(r+8)*SA + ks*8 + q4 + 4];
            }
#pragma unroll
            for (int nt = 0; nt < 4; nt++) {
                int c = wn + nt*8 + g;
                bf[nt][0] = Bs[c*SA + ks*8 + q4];
                bf[nt][1] = Bs[c*SA + ks*8 + q4 + 4];
            }
#pragma unroll
            for (int mt = 0; mt < 4; mt++)
#pragma unroll
                for (int nt = 0; nt < 4; nt++)
                    mma8(acc[mt][nt], af[mt][0], af[mt][1], af[mt][2], af[mt][3],
                         bf[nt][0], bf[nt][1]);
        }
        __syncthreads();
    }
}

// QKV projection: writes [B,H,S,HD] layout
__global__ __launch_bounds__(256, 1)
void qkv_gemm(const float* __restrict__ x, const float* __restrict__ Wq,
              const float* __restrict__ Wk, const float* __restrict__ Wv)
{
    __shared__ float As[128*SA], Bs[128*SA];
    const float* W = (blockIdx.z == 0) ? Wq : (blockIdx.z == 1) ? Wk : Wv;
    float* Out     = (blockIdx.z == 0) ? g_Q : (blockIdx.z == 1) ? g_K : g_V;

    const int bm0 = blockIdx.y*128, bn0 = blockIdx.x*128;
    float acc[4][4][4] = {};
    gemm_mainloop(x, W, As, Bs, bm0, bn0, acc);

    const int t = threadIdx.x;
    const int warp = t >> 5, lane = t & 31, g = lane >> 2, q4 = lane & 3;
    const int wm = (warp & 1) * 64, wn = (warp >> 1) * 32;
#pragma unroll
    for (int mt = 0; mt < 4; mt++) {
        int m = bm0 + wm + mt*16 + g;
        int bb = m >> 11, s = m & 2047;
#pragma unroll
        for (int nt = 0; nt < 4; nt++) {
            int n = bn0 + wn + nt*8 + q4*2;
            int h = n >> 6, d = n & 63;
            float* base = Out + (((size_t)(bb*NH + h)*SEQ + s)*HD + d);
            *(float2*)base = make_float2(acc[mt][nt][0], acc[mt][nt][1]);
            *(float2*)(base + 8*HD) = make_float2(acc[mt][nt][2], acc[mt][nt][3]);
        }
    }
}

// Output projection: out = g_O @ Wo^T + bo
__global__ __launch_bounds__(256, 1)
void proj_gemm(const float* __restrict__ Wo, const float* __restrict__ bo,
               float* __restrict__ outp)
{
    __shared__ float As[128*SA], Bs[128*SA];
    const int bm0 = blockIdx.y*128, bn0 = blockIdx.x*128;
    float acc[4][4][4] = {};
    gemm_mainloop(g_O, Wo, As, Bs, bm0, bn0, acc);

    const int t = threadIdx.x;
    const int warp = t >> 5, lane = t & 31, g = lane >> 2, q4 = lane & 3;
    const int wm = (warp & 1) * 64, wn = (warp >> 1) * 32;
#pragma unroll
    for (int mt = 0; mt < 4; mt++) {
        int m = bm0 + wm + mt*16 + g;
#pragma unroll
        for (int nt = 0; nt < 4; nt++) {
            int n = bn0 + wn + nt*8 + q4*2;
            float2 bv = *(const float2*)(bo + n);
            *(float2*)(outp + (size_t)m*EMB + n) =
                make_float2(acc[mt][nt][0] + bv.x, acc[mt][nt][1] + bv.y);
            *(float2*)(outp + (size_t)(m+8)*EMB + n) =
                make_float2(acc[mt][nt][2] + bv.x, acc[mt][nt][3] + bv.y);
        }
    }
}

// ---------------------------------------------------------------------------
// Causal flash attention, tf32 mma. Block = 128 q-rows of one (b,h).
// 8 warps, each owns 16 q-rows. K/V tiles of 64. P stays in registers
// (D->A fragment remap via shfl).
// ---------------------------------------------------------------------------
#define SK 68   // smem row stride for attn tiles

__global__ __launch_bounds__(256, 1)
void attn_kernel()
{
    extern __shared__ float sm[];
    float* Qs = sm;                 // 128*SK
    float* Ks = sm + 128*SK;        // 64*SK
    float* Vs = Ks + 64*SK;         // 64*SK

    const int t = threadIdx.x;
    const int warp = t >> 5, lane = t & 31, g = lane >> 2, q4 = lane & 3;
    const int qt = (int)gridDim.x - 1 - (int)blockIdx.x;   // big tiles first
    const int h = blockIdx.y, b = blockIdx.z;

    const float* Qg = g_Q + ((size_t)(b*NH + h)*SEQ + qt*128)*HD;
    const float* Kg = g_K + ((size_t)(b*NH + h)*SEQ)*HD;
    const float* Vg = g_V + ((size_t)(b*NH + h)*SEQ)*HD;

    // Load Q tile, fold softmax scale 1/8, convert to tf32
#pragma unroll
    for (int u = 0; u < 8; u++) {
        int idx = u*256 + t;
        int row = idx >> 4, c4 = idx & 15;
        float4 v = ((const float4*)Qg)[idx];
        v.x = to_tf32(v.x*0.125f); v.y = to_tf32(v.y*0.125f);
        v.z = to_tf32(v.z*0.125f); v.w = to_tf32(v.w*0.125f);
        *(float4*)(Qs + row*SK + c4*4) = v;
    }

    float o[8][4] = {};
    float m0 = -1e30f, m1 = -1e30f, l0 = 0.f, l1 = 0.f;
    const int r0 = qt*128 + warp*16 + g;         // global q row (and r0+8)

    const int kbmax = 2*qt + 1;
    for (int kb = 0; kb <= kbmax; kb++) {
        __syncthreads();
#pragma unroll
        for (int u = 0; u < 4; u++) {
            int idx = u*256 + t;
            int row = idx >> 4, c4 = idx & 15;
            float4 kv = ((const float4*)(Kg + (size_t)kb*64*HD))[idx];
            float4 vv = ((const float4*)(Vg + (size_t)kb*64*HD))[idx];
            kv.x = to_tf32(kv.x); kv.y = to_tf32(kv.y);
            kv.z = to_tf32(kv.z); kv.w = to_tf32(kv.w);
            vv.x = to_tf32(vv.x); vv.y = to_tf32(vv.y);
            vv.z = to_tf32(vv.z); vv.w = to_tf32(vv.w);
            *(float4*)(Ks + row*SK + c4*4) = kv;
            *(float4*)(Vs + row*SK + c4*4) = vv;
        }
        __syncthreads();

        // S = Q * K^T (scaled)
        float s[8][4] = {};
#pragma unroll
        for (int ks = 0; ks < 8; ks++) {
            int r = (warp*16 + g)*SK + ks*8 + q4;
            float a0 = Qs[r];
            float a1 = Qs[r + 8*SK];
            float a2 = Qs[r + 4];
            float a3 = Qs[r + 8*SK + 4];
#pragma unroll
            for (int nt = 0; nt < 8; nt++) {
                int c = (nt*8 + g)*SK + ks*8 + q4;
                mma8(s[nt], a0, a1, a2, a3, Ks[c], Ks[c+4]);
            }
        }

        // causal mask + row max
        const int cb = kb*64 + q4*2;
        float mt0 = -1e30f, mt1 = -1e30f;
#pragma unroll
        for (int nt = 0; nt < 8; nt++) {
            int c0 = cb + nt*8, c1 = c0 + 1;
            if (c0 > r0)     s[nt][0] = -1e30f;
            if (c1 > r0)     s[nt][1] = -1e30f;
            if (c0 > r0 + 8) s[nt][2] = -1e30f;
            if (c1 > r0 + 8) s[nt][3] = -1e30f;
            mt0 = fmaxf(mt0, fmaxf(s[nt][0], s[nt][1]));
            mt1 = fmaxf(mt1, fmaxf(s[nt][2], s[nt][3]));
        }
        mt0 = fmaxf(mt0, __shfl_xor_sync(0xffffffffu, mt0, 1));
        mt0 = fmaxf(mt0, __shfl_xor_sync(0xffffffffu, mt0, 2));
        mt1 = fmaxf(mt1, __shfl_xor_sync(0xffffffffu, mt1, 1));
        mt1 = fmaxf(mt1, __shfl_xor_sync(0xffffffffu, mt1, 2));

        float mn0 = fmaxf(m0, mt0), mn1 = fmaxf(m1, mt1);
        float cr0 = __expf(m0 - mn0), cr1 = __expf(m1 - mn1);
        m0 = mn0; m1 = mn1;
        l0 *= cr0; l1 *= cr1;
#pragma unroll
        for (int dt = 0; dt < 8; dt++) {
            o[dt][0] *= cr0; o[dt][1] *= cr0;
            o[dt][2] *= cr1; o[dt][3] *= cr1;
        }
        // P = exp(S - m), accumulate l, convert to tf32 in place
#pragma unroll
        for (int nt = 0; nt < 8; nt++) {
            s[nt][0] = __expf(s[nt][0] - m0);
            s[nt][1] = __expf(s[nt][1] - m0);
            s[nt][2] = __expf(s[nt][2] - m1);
            s[nt][3] = __expf(s[nt][3] - m1);
            l0 += s[nt][0] + s[nt][1];
            l1 += s[nt][2] + s[nt][3];
            s[nt][0] = to_tf32(s[nt][0]); s[nt][1] = to_tf32(s[nt][1]);
            s[nt][2] = to_tf32(s[nt][2]); s[nt][3] = to_tf32(s[nt][3]);
        }

        // O += P * V  (A fragments built from s[] via shfl remap)
        const int base = lane & 28;
        const int lA = base + (q4 >> 1), lB = lA + 2;
        const bool odd = (q4 & 1);
#pragma unroll
        for (int ks = 0; ks < 8; ks++) {
            float x0 = __shfl_sync(0xffffffffu, s[ks][0], lA);
            float y0 = __shfl_sync(0xffffffffu, s[ks][1], lA);
            float x2 = __shfl_sync(0xffffffffu, s[ks][0], lB);
            float y2 = __shfl_sync(0xffffffffu, s[ks][1], lB);
            float x1 = __shfl_sync(0xffffffffu, s[ks][2], lA);
            float y1 = __shfl_sync(0xffffffffu, s[ks][3], lA);
            float x3 = __shfl_sync(0xffffffffu, s[ks][2], lB);
            float y3 = __shfl_sync(0xffffffffu, s[ks][3], lB);
            float a0 = odd ? y0 : x0;
            float a1 = odd ? y1 : x1;
            float a2 = odd ? y2 : x2;
            float a3 = odd ? y3 : x3;
#pragma unroll
            for (int dt = 0; dt < 8; dt++) {
                int vb = (ks*8 + q4)*SK + dt*8 + g;
                mma8(o[dt], a0, a1, a2, a3, Vs[vb], Vs[vb + 4*SK]);
            }
        }
    }

    // finalize
    l0 += __shfl_xor_sync(0xffffffffu, l0, 1);
    l0 += __shfl_xor_sync(0xffffffffu, l0, 2);
    l1 += __shfl_xor_sync(0xffffffffu, l1, 1);
    l1 += __shfl_xor_sync(0xffffffffu, l1, 2);
    float i0 = 1.f / l0, i1 = 1.f / l1;

    float* Ob = g_O + ((size_t)b*SEQ + r0)*EMB + h*HD;
#pragma unroll
    for (int dt = 0; dt < 8; dt++) {
        int c = dt*8 + q4*2;
        *(float2*)(Ob + c)         = make_float2(o[dt][0]*i0, o[dt][1]*i0);
        *(float2*)(Ob + 8*EMB + c) = make_float2(o[dt][2]*i1, o[dt][3]*i1);
    }
}

// ---------------------------------------------------------------------------
extern "C" void kernel_launch(void* const* d_in, const int* in_sizes, int n_in,
                              void* d_out, int out_size)
{
    const float* x  = (const float*)d_in[0];
    const float* Wq = (const float*)d_in[1];
    const float* Wk = (const float*)d_in[2];
    const float* Wv = (const float*)d_in[3];
    const float* Wo = (const float*)d_in[4];
    const float* bo = (const float*)d_in[5];
    float* out = (float*)d_out;

    const int attn_smem = (128*SK + 64*SK + 64*SK) * sizeof(float);  // 69632 B
    cudaFuncSetAttribute(attn_kernel, cudaFuncAttributeMaxDynamicSharedMemorySize,
                         attn_smem);

    qkv_gemm<<<dim3(EMB/128, (BATCH*SEQ)/128, 3), 256>>>(x, Wq, Wk, Wv);
    attn_kernel<<<dim3(SEQ/128, NH, BATCH), 256, attn_smem>>>();
    proj_gemm<<<dim3(EMB/128, (BATCH*SEQ)/128), 256>>>(Wo, bo, out);
}

// round 4
// speedup vs baseline: 10.8579x; 1.1897x over previous
#include <cuda_runtime.h>
#include <cstdint>

#define SEQ  2048
#define EMB  1024
#define NH   16
#define HD   64
#define BATCH 4

// Scratch (no cudaMalloc allowed)
__device__ float g_Q[BATCH*NH*SEQ*HD];
__device__ float g_K[BATCH*NH*SEQ*HD];
__device__ float g_V[BATCH*NH*SEQ*HD];
__device__ float g_O[BATCH*SEQ*EMB];

__device__ __forceinline__ float to_tf32(float x) {
    float r; asm("cvt.rna.tf32.f32 %0, %1;" : "=f"(r) : "f"(x)); return r;
}
__device__ __forceinline__ float4 cvt4(float4 v) {
    v.x = to_tf32(v.x); v.y = to_tf32(v.y);
    v.z = to_tf32(v.z); v.w = to_tf32(v.w);
    return v;
}

// D += A(16x8,row) * B(8x8,col)  tf32
__device__ __forceinline__ void mma8(float* d, float a0, float a1, float a2, float a3,
                                     float b0, float b1) {
    uint32_t A0=__float_as_uint(a0), A1=__float_as_uint(a1),
             A2=__float_as_uint(a2), A3=__float_as_uint(a3);
    uint32_t B0=__float_as_uint(b0), B1=__float_as_uint(b1);
    asm volatile("mma.sync.aligned.m16n8k8.row.col.f32.tf32.tf32.f32 "
                 "{%0,%1,%2,%3},{%4,%5,%6,%7},{%8,%9},{%0,%1,%2,%3};"
                 : "+f"(d[0]), "+f"(d[1]), "+f"(d[2]), "+f"(d[3])
                 : "r"(A0), "r"(A1), "r"(A2), "r"(A3), "r"(B0), "r"(B1));
}

#define SA 36   // smem row stride (floats): 36 % 32 = 4 -> conflict-free frag loads

// ---------------------------------------------------------------------------
// NT GEMM mainloop, double-buffered + register prefetch.
// C[128x128] = A[128xK] * B[128xK]^T, tf32 mma.
// 256 threads = 8 warps (2 M x 4 N), warp tile 64x32, BK = 32.
// Asb/Bsb each hold 2 buffers of 128*SA floats.
// ---------------------------------------------------------------------------
__device__ __forceinline__ void gemm_mainloop(const float* __restrict__ A,
                                              const float* __restrict__ B,
                                              float* Asb, float* Bsb,
                                              int bm0, int bn0,
                                              float acc[4][4][4]) {
    const int t = threadIdx.x;
    const int warp = t >> 5, lane = t & 31, g = lane >> 2, q4 = lane & 3;
    const int wm = (warp & 1) * 64, wn = (warp >> 1) * 32;
    const int lrow = t >> 3, lc4 = t & 7;     // loader: row base, float4 col

    float4 pa[4], pb[4];
    // prefetch k0 = 0
#pragma unroll
    for (int u = 0; u < 4; u++) {
        int row = u*32 + lrow;
        pa[u] = *(const float4*)(A + (size_t)(bm0+row)*EMB + lc4*4);
        pb[u] = *(const float4*)(B + (size_t)(bn0+row)*EMB + lc4*4);
    }
#pragma unroll
    for (int u = 0; u < 4; u++) {
        int row = u*32 + lrow;
        *(float4*)(Asb + row*SA + lc4*4) = cvt4(pa[u]);
        *(float4*)(Bsb + row*SA + lc4*4) = cvt4(pb[u]);
    }
    __syncthreads();

    int buf = 0;
    for (int k0 = 0; k0 < EMB; k0 += 32) {
        float* As = Asb + buf*128*SA;
        float* Bs = Bsb + buf*128*SA;
        const bool more = (k0 + 32 < EMB);
        if (more) {
#pragma unroll
            for (int u = 0; u < 4; u++) {
                int row = u*32 + lrow;
                pa[u] = *(const float4*)(A + (size_t)(bm0+row)*EMB + k0+32 + lc4*4);
                pb[u] = *(const float4*)(B + (size_t)(bn0+row)*EMB + k0+32 + lc4*4);
            }
        }
#pragma unroll
        for (int ks = 0; ks < 4; ks++) {
            float af[4][4], bf[4][2];
#pragma unroll
            for (int mt = 0; mt < 4; mt++) {
                int r = wm + mt*16 + g;
                af[mt][0] = As[r*SA     + ks*8 + q4];
                af[mt][1] = As[(r+8)*SA + ks*8 + q4];
                af[mt][2] = As[r*SA     + ks*8 + q4 + 4];
                af[mt][3] = As[(r+8)*SA + ks*8 + q4 + 4];
            }
#pragma unroll
            for (int nt = 0; nt < 4; nt++) {
                int c = wn + nt*8 + g;
                bf[nt][0] = Bs[c*SA + ks*8 + q4];
                bf[nt][1] = Bs[c*SA + ks*8 + q4 + 4];
            }
#pragma unroll
            for (int mt = 0; mt < 4; mt++)
#pragma unroll
                for (int nt = 0; nt < 4; nt++)
                    mma8(acc[mt][nt], af[mt][0], af[mt][1], af[mt][2], af[mt][3],
                         bf[nt][0], bf[nt][1]);
        }
        if (more) {
            float* An = Asb + (buf^1)*128*SA;
            float* Bn = Bsb + (buf^1)*128*SA;
#pragma unroll
            for (int u = 0; u < 4; u++) {
                int row = u*32 + lrow;
                *(float4*)(An + row*SA + lc4*4) = cvt4(pa[u]);
                *(float4*)(Bn + row*SA + lc4*4) = cvt4(pb[u]);
            }
        }
        __syncthreads();
        buf ^= 1;
    }
}

// QKV projection: writes [B,H,S,HD] layout
__global__ __launch_bounds__(256, 1)
void qkv_gemm(const float* __restrict__ x, const float* __restrict__ Wq,
              const float* __restrict__ Wk, const float* __restrict__ Wv)
{
    __shared__ float As[2*128*SA], Bs[2*128*SA];
    const float* W = (blockIdx.z == 0) ? Wq : (blockIdx.z == 1) ? Wk : Wv;
    float* Out     = (blockIdx.z == 0) ? g_Q : (blockIdx.z == 1) ? g_K : g_V;

    const int bm0 = blockIdx.y*128, bn0 = blockIdx.x*128;
    float acc[4][4][4] = {};
    gemm_mainloop(x, W, As, Bs, bm0, bn0, acc);

    const int t = threadIdx.x;
    const int warp = t >> 5, lane = t & 31, g = lane >> 2, q4 = lane & 3;
    const int wm = (warp & 1) * 64, wn = (warp >> 1) * 32;
#pragma unroll
    for (int mt = 0; mt < 4; mt++) {
        int m = bm0 + wm + mt*16 + g;
        int bb = m >> 11, s = m & 2047;
#pragma unroll
        for (int nt = 0; nt < 4; nt++) {
            int n = bn0 + wn + nt*8 + q4*2;
            int h = n >> 6, d = n & 63;
            float* base = Out + (((size_t)(bb*NH + h)*SEQ + s)*HD + d);
            *(float2*)base = make_float2(acc[mt][nt][0], acc[mt][nt][1]);
            *(float2*)(base + 8*HD) = make_float2(acc[mt][nt][2], acc[mt][nt][3]);
        }
    }
}

// Output projection: out = g_O @ Wo^T + bo
__global__ __launch_bounds__(256, 1)
void proj_gemm(const float* __restrict__ Wo, const float* __restrict__ bo,
               float* __restrict__ outp)
{
    __shared__ float As[2*128*SA], Bs[2*128*SA];
    const int bm0 = blockIdx.y*128, bn0 = blockIdx.x*128;
    float acc[4][4][4] = {};
    gemm_mainloop(g_O, Wo, As, Bs, bm0, bn0, acc);

    const int t = threadIdx.x;
    const int warp = t >> 5, lane = t & 31, g = lane >> 2, q4 = lane & 3;
    const int wm = (warp & 1) * 64, wn = (warp >> 1) * 32;
#pragma unroll
    for (int mt = 0; mt < 4; mt++) {
        int m = bm0 + wm + mt*16 + g;
#pragma unroll
        for (int nt = 0; nt < 4; nt++) {
            int n = bn0 + wn + nt*8 + q4*2;
            float2 bv = *(const float2*)(bo + n);
            *(float2*)(outp + (size_t)m*EMB + n) =
                make_float2(acc[mt][nt][0] + bv.x, acc[mt][nt][1] + bv.y);
            *(float2*)(outp + (size_t)(m+8)*EMB + n) =
                make_float2(acc[mt][nt][2] + bv.x, acc[mt][nt][3] + bv.y);
        }
    }
}

// ---------------------------------------------------------------------------
// Causal flash attention, tf32 mma, double-buffered K/V + register prefetch.
// Block = 128 q-rows of one (b,h). 8 warps, each owns 16 q-rows.
// ---------------------------------------------------------------------------
#define SK 68   // smem row stride for attn tiles

__global__ __launch_bounds__(256, 1)
void attn_kernel()
{
    extern __shared__ float sm[];
    float* Qs  = sm;                      // 128*SK
    float* Ksb = sm + 128*SK;             // 2 buffers of 64*SK
    float* Vsb = Ksb + 2*64*SK;           // 2 buffers of 64*SK

    const int t = threadIdx.x;
    const int warp = t >> 5, lane = t & 31, g = lane >> 2, q4 = lane & 3;
    const int qt = (int)gridDim.x - 1 - (int)blockIdx.x;   // big tiles first
    const int h = blockIdx.y, b = blockIdx.z;

    const float* Qg = g_Q + ((size_t)(b*NH + h)*SEQ + qt*128)*HD;
    const float4* KgF = (const float4*)(g_K + ((size_t)(b*NH + h)*SEQ)*HD);
    const float4* VgF = (const float4*)(g_V + ((size_t)(b*NH + h)*SEQ)*HD);

    const int lrow = t >> 4, lc4 = t & 15;   // loader indices for 64x64 tiles

    // Load Q tile, fold softmax scale 1/8, convert to tf32
#pragma unroll
    for (int u = 0; u < 8; u++) {
        int idx = u*256 + t;
        int row = idx >> 4, c4 = idx & 15;
        float4 v = ((const float4*)Qg)[idx];
        v.x = to_tf32(v.x*0.125f); v.y = to_tf32(v.y*0.125f);
        v.z = to_tf32(v.z*0.125f); v.w = to_tf32(v.w*0.125f);
        *(float4*)(Qs + row*SK + c4*4) = v;
    }

    // Prefetch kb = 0 K/V into buffer 0
    float4 pk[4], pv[4];
#pragma unroll
    for (int u = 0; u < 4; u++) {
        int idx = u*256 + t;
        pk[u] = KgF[idx];
        pv[u] = VgF[idx];
    }
#pragma unroll
    for (int u = 0; u < 4; u++) {
        int row = u*16 + lrow;
        *(float4*)(Ksb + row*SK + lc4*4) = cvt4(pk[u]);
        *(float4*)(Vsb + row*SK + lc4*4) = cvt4(pv[u]);
    }
    __syncthreads();

    float o[8][4] = {};
    float m0 = -1e30f, m1 = -1e30f, l0 = 0.f, l1 = 0.f;
    const int r0 = qt*128 + warp*16 + g;         // global q row (and r0+8)

    const int kbmax = 2*qt + 1;
    int buf = 0;
    for (int kb = 0; kb <= kbmax; kb++) {
        float* Ks = Ksb + buf*64*SK;
        float* Vs = Vsb + buf*64*SK;
        const bool more = (kb < kbmax);
        if (more) {
#pragma unroll
            for (int u = 0; u < 4; u++) {
                int idx = (kb+1)*1024 + u*256 + t;
                pk[u] = KgF[idx];
                pv[u] = VgF[idx];
            }
        }

        // S = Q * K^T (scaled)
        float s[8][4] = {};
#pragma unroll
        for (int ks = 0; ks < 8; ks++) {
            int r = (warp*16 + g)*SK + ks*8 + q4;
            float a0 = Qs[r];
            float a1 = Qs[r + 8*SK];
            float a2 = Qs[r + 4];
            float a3 = Qs[r + 8*SK + 4];
#pragma unroll
            for (int nt = 0; nt < 8; nt++) {
                int c = (nt*8 + g)*SK + ks*8 + q4;
                mma8(s[nt], a0, a1, a2, a3, Ks[c], Ks[c+4]);
            }
        }

        // causal mask + row max
        const int cb = kb*64 + q4*2;
        float mt0 = -1e30f, mt1 = -1e30f;
#pragma unroll
        for (int nt = 0; nt < 8; nt++) {
            int c0 = cb + nt*8, c1 = c0 + 1;
            if (c0 > r0)     s[nt][0] = -1e30f;
            if (c1 > r0)     s[nt][1] = -1e30f;
            if (c0 > r0 + 8) s[nt][2] = -1e30f;
            if (c1 > r0 + 8) s[nt][3] = -1e30f;
            mt0 = fmaxf(mt0, fmaxf(s[nt][0], s[nt][1]));
            mt1 = fmaxf(mt1, fmaxf(s[nt][2], s[nt][3]));
        }
        mt0 = fmaxf(mt0, __shfl_xor_sync(0xffffffffu, mt0, 1));
        mt0 = fmaxf(mt0, __shfl_xor_sync(0xffffffffu, mt0, 2));
        mt1 = fmaxf(mt1, __shfl_xor_sync(0xffffffffu, mt1, 1));
        mt1 = fmaxf(mt1, __shfl_xor_sync(0xffffffffu, mt1, 2));

        float mn0 = fmaxf(m0, mt0), mn1 = fmaxf(m1, mt1);
        float cr0 = __expf(m0 - mn0), cr1 = __expf(m1 - mn1);
        m0 = mn0; m1 = mn1;
        l0 *= cr0; l1 *= cr1;
#pragma unroll
        for (int dt = 0; dt < 8; dt++) {
            o[dt][0] *= cr0; o[dt][1] *= cr0;
            o[dt][2] *= cr1; o[dt][3] *= cr1;
        }
        // P = exp(S - m), accumulate l, convert to tf32 in place
#pragma unroll
        for (int nt = 0; nt < 8; nt++) {
            s[nt][0] = __expf(s[nt][0] - m0);
            s[nt][1] = __expf(s[nt][1] - m0);
            s[nt][2] = __expf(s[nt][2] - m1);
            s[nt][3] = __expf(s[nt][3] - m1);
            l0 += s[nt][0] + s[nt][1];
            l1 += s[nt][2] + s[nt][3];
            s[nt][0] = to_tf32(s[nt][0]); s[nt][1] = to_tf32(s[nt][1]);
            s[nt][2] = to_tf32(s[nt][2]); s[nt][3] = to_tf32(s[nt][3]);
        }

        // O += P * V  (A fragments built from s[] via shfl remap)
        const int base = lane & 28;
        const int lA = base + (q4 >> 1), lB = lA + 2;
        const bool odd = (q4 & 1);
#pragma unroll
        for (int ks = 0; ks < 8; ks++) {
            float x0 = __shfl_sync(0xffffffffu, s[ks][0], lA);
            float y0 = __shfl_sync(0xffffffffu, s[ks][1], lA);
            float x2 = __shfl_sync(0xffffffffu, s[ks][0], lB);
            float y2 = __shfl_sync(0xffffffffu, s[ks][1], lB);
            float x1 = __shfl_sync(0xffffffffu, s[ks][2], lA);
            float y1 = __shfl_sync(0xffffffffu, s[ks][3], lA);
            float x3 = __shfl_sync(0xffffffffu, s[ks][2], lB);
            float y3 = __shfl_sync(0xffffffffu, s[ks][3], lB);
            float a0 = odd ? y0 : x0;
            float a1 = odd ? y1 : x1;
            float a2 = odd ? y2 : x2;
            float a3 = odd ? y3 : x3;
#pragma unroll
            for (int dt = 0; dt < 8; dt++) {
                int vb = (ks*8 + q4)*SK + dt*8 + g;
                mma8(o[dt], a0, a1, a2, a3, Vs[vb], Vs[vb + 4*SK]);
            }
        }

        if (more) {
            float* Kn = Ksb + (buf^1)*64*SK;
            float* Vn = Vsb + (buf^1)*64*SK;
#pragma unroll
            for (int u = 0; u < 4; u++) {
                int row = u*16 + lrow;
                *(float4*)(Kn + row*SK + lc4*4) = cvt4(pk[u]);
                *(float4*)(Vn + row*SK + lc4*4) = cvt4(pv[u]);
            }
        }
        __syncthreads();
        buf ^= 1;
    }

    // finalize
    l0 += __shfl_xor_sync(0xffffffffu, l0, 1);
    l0 += __shfl_xor_sync(0xffffffffu, l0, 2);
    l1 += __shfl_xor_sync(0xffffffffu, l1, 1);
    l1 += __shfl_xor_sync(0xffffffffu, l1, 2);
    float i0 = 1.f / l0, i1 = 1.f / l1;

    float* Ob = g_O + ((size_t)b*SEQ + r0)*EMB + h*HD;
#pragma unroll
    for (int dt = 0; dt < 8; dt++) {
        int c = dt*8 + q4*2;
        *(float2*)(Ob + c)         = make_float2(o[dt][0]*i0, o[dt][1]*i0);
        *(float2*)(Ob + 8*EMB + c) = make_float2(o[dt][2]*i1, o[dt][3]*i1);
    }
}

// ---------------------------------------------------------------------------
extern "C" void kernel_launch(void* const* d_in, const int* in_sizes, int n_in,
                              void* d_out, int out_size)
{
    const float* x  = (const float*)d_in[0];
    const float* Wq = (const float*)d_in[1];
    const float* Wk = (const float*)d_in[2];
    const float* Wv = (const float*)d_in[3];
    const float* Wo = (const float*)d_in[4];
    const float* bo = (const float*)d_in[5];
    float* out = (float*)d_out;

    const int attn_smem = (128*SK + 4*64*SK) * sizeof(float);  // 104448 B
    cudaFuncSetAttribute(attn_kernel, cudaFuncAttributeMaxDynamicSharedMemorySize,
                         attn_smem);

    qkv_gemm<<<dim3(EMB/128, (BATCH*SEQ)/128, 3), 256>>>(x, Wq, Wk, Wv);
    attn_kernel<<<dim3(SEQ/128, NH, BATCH), 256, attn_smem>>>();
    proj_gemm<<<dim3(EMB/128, (BATCH*SEQ)/128), 256>>>(Wo, bo, out);
}

// round 9
// speedup vs baseline: 11.5743x; 1.0660x over previous
#include <cuda_runtime.h>
#include <cstdint>

#define SEQ  2048
#define EMB  1024
#define NH   16
#define HD   64
#define BATCH 4

// Scratch (no cudaMalloc allowed)
__device__ float g_Q[BATCH*NH*SEQ*HD];
__device__ float g_K[BATCH*NH*SEQ*HD];
__device__ float g_V[BATCH*NH*SEQ*HD];
__device__ float g_O[BATCH*SEQ*EMB];

__device__ __forceinline__ float to_tf32(float x) {
    float r; asm("cvt.rna.tf32.f32 %0, %1;" : "=f"(r) : "f"(x)); return r;
}

__device__ __forceinline__ void cp16(float* smem_dst, const float* gmem_src) {
    uint32_t s = (uint32_t)__cvta_generic_to_shared(smem_dst);
    asm volatile("cp.async.cg.shared.global [%0], [%1], 16;" :: "r"(s), "l"(gmem_src));
}
__device__ __forceinline__ void cp_commit() {
    asm volatile("cp.async.commit_group;");
}
template<int N>
__device__ __forceinline__ void cp_wait() {
    asm volatile("cp.async.wait_group %0;" :: "n"(N));
}

// D += A(16x8,row) * B(8x8,col)  tf32
__device__ __forceinline__ void mma8(float* d, float a0, float a1, float a2, float a3,
                                     float b0, float b1) {
    uint32_t A0=__float_as_uint(a0), A1=__float_as_uint(a1),
             A2=__float_as_uint(a2), A3=__float_as_uint(a3);
    uint32_t B0=__float_as_uint(b0), B1=__float_as_uint(b1);
    asm volatile("mma.sync.aligned.m16n8k8.row.col.f32.tf32.tf32.f32 "
                 "{%0,%1,%2,%3},{%4,%5,%6,%7},{%8,%9},{%0,%1,%2,%3};"
                 : "+f"(d[0]), "+f"(d[1]), "+f"(d[2]), "+f"(d[3])
                 : "r"(A0), "r"(A1), "r"(A2), "r"(A3), "r"(B0), "r"(B1));
}

#define SA 36   // smem row stride (floats): 36 % 32 = 4 -> conflict-free frag loads
#define GEMM_STAGE (2*128*SA)            // A + B per stage (floats)
#define GEMM_SMEM  (2*GEMM_STAGE*4)      // bytes, 2 stages

// ---------------------------------------------------------------------------
// NT GEMM mainloop: C[128x128] = A[128xK]*B[128xK]^T, tf32 mma, cp.async
// double-buffered, raw fp32 in smem, cvt.rna at fragment load.
// 256 threads = 8 warps (2 M x 4 N), warp tile 64x32, BK = 32.
// ---------------------------------------------------------------------------
__device__ __forceinline__ void gemm_issue(const float* __restrict__ A,
                                           const float* __restrict__ B,
                                           float* stage, int bm0, int bn0, int k0) {
    const int t = threadIdx.x;
    const int lrow = t >> 3, lc4 = t & 7;
    float* As = stage;
    float* Bs = stage + 128*SA;
#pragma unroll
    for (int u = 0; u < 4; u++) {
        int row = u*32 + lrow;
        cp16(As + row*SA + lc4*4, A + (size_t)(bm0+row)*EMB + k0 + lc4*4);
        cp16(Bs + row*SA + lc4*4, B + (size_t)(bn0+row)*EMB + k0 + lc4*4);
    }
}

__device__ __forceinline__ void gemm_mainloop(const float* __restrict__ A,
                                              const float* __restrict__ B,
                                              float* sm, int bm0, int bn0,
                                              float acc[4][4][4]) {
    const int t = threadIdx.x;
    const int warp = t >> 5, lane = t & 31, g = lane >> 2, q4 = lane & 3;
    const int wm = (warp & 1) * 64, wn = (warp >> 1) * 32;

    gemm_issue(A, B, sm, bm0, bn0, 0);
    cp_commit();

    int buf = 0;
    for (int k0 = 0; k0 < EMB; k0 += 32) {
        const bool more = (k0 + 32 < EMB);
        if (more) {
            gemm_issue(A, B, sm + (buf^1)*GEMM_STAGE, bm0, bn0, k0 + 32);
            cp_commit();
            cp_wait<1>();
        } else {
            cp_wait<0>();
        }
        __syncthreads();

        const float* As = sm + buf*GEMM_STAGE;
        const float* Bs = As + 128*SA;
#pragma unroll
        for (int ks = 0; ks < 4; ks++) {
            float af[4][4], bf[4][2];
#pragma unroll
            for (int mt = 0; mt < 4; mt++) {
                int r = wm + mt*16 + g;
                af[mt][0] = to_tf32(As[r*SA     + ks*8 + q4]);
                af[mt][1] = to_tf32(As[(r+8)*SA + ks*8 + q4]);
                af[mt][2] = to_tf32(As[r*SA     + ks*8 + q4 + 4]);
                af[mt][3] = to_tf32(As[(r+8)*SA + ks*8 + q4 + 4]);
            }
#pragma unroll
            for (int nt = 0; nt < 4; nt++) {
                int c = wn + nt*8 + g;
                bf[nt][0] = to_tf32(Bs[c*SA + ks*8 + q4]);
                bf[nt][1] = to_tf32(Bs[c*SA + ks*8 + q4 + 4]);
            }
#pragma unroll
            for (int mt = 0; mt < 4; mt++)
#pragma unroll
                for (int nt = 0; nt < 4; nt++)
                    mma8(acc[mt][nt], af[mt][0], af[mt][1], af[mt][2], af[mt][3],
                         bf[nt][0], bf[nt][1]);
        }
        __syncthreads();
        buf ^= 1;
    }
}

// QKV projection: writes [B,H,S,HD] layout
__global__ __launch_bounds__(256, 2)
void qkv_gemm(const float* __restrict__ x, const float* __restrict__ Wq,
              const float* __restrict__ Wk, const float* __restrict__ Wv)
{
    extern __shared__ float sm[];
    const float* W = (blockIdx.z == 0) ? Wq : (blockIdx.z == 1) ? Wk : Wv;
    float* Out     = (blockIdx.z == 0) ? g_Q : (blockIdx.z == 1) ? g_K : g_V;

    const int bm0 = blockIdx.y*128, bn0 = blockIdx.x*128;
    float acc[4][4][4] = {};
    gemm_mainloop(x, W, sm, bm0, bn0, acc);

    const int t = threadIdx.x;
    const int warp = t >> 5, lane = t & 31, g = lane >> 2, q4 = lane & 3;
    const int wm = (warp & 1) * 64, wn = (warp >> 1) * 32;
#pragma unroll
    for (int mt = 0; mt < 4; mt++) {
        int m = bm0 + wm + mt*16 + g;
        int bb = m >> 11, s = m & 2047;
#pragma unroll
        for (int nt = 0; nt < 4; nt++) {
            int n = bn0 + wn + nt*8 + q4*2;
            int h = n >> 6, d = n & 63;
            float* base = Out + (((size_t)(bb*NH + h)*SEQ + s)*HD + d);
            *(float2*)base = make_float2(acc[mt][nt][0], acc[mt][nt][1]);
            *(float2*)(base + 8*HD) = make_float2(acc[mt][nt][2], acc[mt][nt][3]);
        }
    }
}

// Output projection: out = g_O @ Wo^T + bo
__global__ __launch_bounds__(256, 2)
void proj_gemm(const float* __restrict__ Wo, const float* __restrict__ bo,
               float* __restrict__ outp)
{
    extern __shared__ float sm[];
    const int bm0 = blockIdx.y*128, bn0 = blockIdx.x*128;
    float acc[4][4][4] = {};
    gemm_mainloop(g_O, Wo, sm, bm0, bn0, acc);

    const int t = threadIdx.x;
    const int warp = t >> 5, lane = t & 31, g = lane >> 2, q4 = lane & 3;
    const int wm = (warp & 1) * 64, wn = (warp >> 1) * 32;
#pragma unroll
    for (int mt = 0; mt < 4; mt++) {
        int m = bm0 + wm + mt*16 + g;
#pragma unroll
        for (int nt = 0; nt < 4; nt++) {
            int n = bn0 + wn + nt*8 + q4*2;
            float2 bv = *(const float2*)(bo + n);
            *(float2*)(outp + (size_t)m*EMB + n) =
                make_float2(acc[mt][nt][0] + bv.x, acc[mt][nt][1] + bv.y);
            *(float2*)(outp + (size_t)(m+8)*EMB + n) =
                make_float2(acc[mt][nt][2] + bv.x, acc[mt][nt][3] + bv.y);
        }
    }
}

// ---------------------------------------------------------------------------
// Causal flash attention, tf32 mma, cp.async double-buffered K/V (raw fp32,
// cvt at fragment load). Block = 128 q-rows of one (b,h). 8 warps.
// ---------------------------------------------------------------------------
#define SK 68   // smem row stride for attn tiles
#define KV_STAGE (64*SK)

__global__ __launch_bounds__(256, 2)
void attn_kernel()
{
    extern __shared__ float sm[];
    float* Qs  = sm;                      // 128*SK (tf32, converted once)
    float* Ksb = sm + 128*SK;             // 2 stages of 64*SK (raw fp32)
    float* Vsb = Ksb + 2*KV_STAGE;        // 2 stages of 64*SK (raw fp32)

    const int t = threadIdx.x;
    const int warp = t >> 5, lane = t & 31, g = lane >> 2, q4 = lane & 3;
    const int qt = (int)gridDim.x - 1 - (int)blockIdx.x;   // big tiles first
    const int h = blockIdx.y, b = blockIdx.z;

    const float* Qg = g_Q + ((size_t)(b*NH + h)*SEQ + qt*128)*HD;
    const float* Kg = g_K + ((size_t)(b*NH + h)*SEQ)*HD;
    const float* Vg = g_V + ((size_t)(b*NH + h)*SEQ)*HD;

    const int lrow = t >> 4, lc4 = t & 15;   // loader for 64x64 tiles

    // Issue kb=0 K/V loads (raw)
#pragma unroll
    for (int u = 0; u < 4; u++) {
        int row = u*16 + lrow;
        cp16(Ksb + row*SK + lc4*4, Kg + (size_t)row*HD + lc4*4);
        cp16(Vsb + row*SK + lc4*4, Vg + (size_t)row*HD + lc4*4);
    }
    cp_commit();

    // Load Q tile, fold softmax scale 1/8, convert to tf32
#pragma unroll
    for (int u = 0; u < 8; u++) {
        int idx = u*256 + t;
        int row = idx >> 4, c4 = idx & 15;
        float4 v = ((const float4*)Qg)[idx];
        v.x = to_tf32(v.x*0.125f); v.y = to_tf32(v.y*0.125f);
        v.z = to_tf32(v.z*0.125f); v.w = to_tf32(v.w*0.125f);
        *(float4*)(Qs + row*SK + c4*4) = v;
    }

    float o[8][4] = {};
    float m0 = -1e30f, m1 = -1e30f, l0 = 0.f, l1 = 0.f;
    const int r0 = qt*128 + warp*16 + g;         // global q row (and r0+8)

    const int kbmax = 2*qt + 1;
    int buf = 0;
    for (int kb = 0; kb <= kbmax; kb++) {
        const bool more = (kb < kbmax);
        if (more) {
            float* Kn = Ksb + (buf^1)*KV_STAGE;
            float* Vn = Vsb + (buf^1)*KV_STAGE;
            const float* Kgn = Kg + (size_t)(kb+1)*64*HD;
            const float* Vgn = Vg + (size_t)(kb+1)*64*HD;
#pragma unroll
            for (int u = 0; u < 4; u++) {
                int row = u*16 + lrow;
                cp16(Kn + row*SK + lc4*4, Kgn + (size_t)row*HD + lc4*4);
                cp16(Vn + row*SK + lc4*4, Vgn + (size_t)row*HD + lc4*4);
            }
            cp_commit();
            cp_wait<1>();
        } else {
            cp_wait<0>();
        }
        __syncthreads();

        const float* Ks = Ksb + buf*KV_STAGE;
        const float* Vs = Vsb + buf*KV_STAGE;

        // S = Q * K^T (scaled)
        float s[8][4] = {};
#pragma unroll
        for (int ks = 0; ks < 8; ks++) {
            int r = (warp*16 + g)*SK + ks*8 + q4;
            float a0 = Qs[r];
            float a1 = Qs[r + 8*SK];
            float a2 = Qs[r + 4];
            float a3 = Qs[r + 8*SK + 4];
#pragma unroll
            for (int nt = 0; nt < 8; nt++) {
                int c = (nt*8 + g)*SK + ks*8 + q4;
                mma8(s[nt], a0, a1, a2, a3, to_tf32(Ks[c]), to_tf32(Ks[c+4]));
            }
        }

        // causal mask + row max
        const int cb = kb*64 + q4*2;
        float mt0 = -1e30f, mt1 = -1e30f;
#pragma unroll
        for (int nt = 0; nt < 8; nt++) {
            int c0 = cb + nt*8, c1 = c0 + 1;
            if (c0 > r0)     s[nt][0] = -1e30f;
            if (c1 > r0)     s[nt][1] = -1e30f;
            if (c0 > r0 + 8) s[nt][2] = -1e30f;
            if (c1 > r0 + 8) s[nt][3] = -1e30f;
            mt0 = fmaxf(mt0, fmaxf(s[nt][0], s[nt][1]));
            mt1 = fmaxf(mt1, fmaxf(s[nt][2], s[nt][3]));
        }
        mt0 = fmaxf(mt0, __shfl_xor_sync(0xffffffffu, mt0, 1));
        mt0 = fmaxf(mt0, __shfl_xor_sync(0xffffffffu, mt0, 2));
        mt1 = fmaxf(mt1, __shfl_xor_sync(0xffffffffu, mt1, 1));
        mt1 = fmaxf(mt1, __shfl_xor_sync(0xffffffffu, mt1, 2));

        float mn0 = fmaxf(m0, mt0), mn1 = fmaxf(m1, mt1);
        float cr0 = __expf(m0 - mn0), cr1 = __expf(m1 - mn1);
        m0 = mn0; m1 = mn1;
        l0 *= cr0; l1 *= cr1;
#pragma unroll
        for (int dt = 0; dt < 8; dt++) {
            o[dt][0] *= cr0; o[dt][1] *= cr0;
            o[dt][2] *= cr1; o[dt][3] *= cr1;
        }
        // P = exp(S - m), accumulate l, convert to tf32 in place
#pragma unroll
        for (int nt = 0; nt < 8; nt++) {
            s[nt][0] = __expf(s[nt][0] - m0);
            s[nt][1] = __expf(s[nt][1] - m0);
            s[nt][2] = __expf(s[nt][2] - m1);
            s[nt][3] = __expf(s[nt][3] - m1);
            l0 += s[nt][0] + s[nt][1];
            l1 += s[nt][2] + s[nt][3];
            s[nt][0] = to_tf32(s[nt][0]); s[nt][1] = to_tf32(s[nt][1]);
            s[nt][2] = to_tf32(s[nt][2]); s[nt][3] = to_tf32(s[nt][3]);
        }

        // O += P * V  (A fragments built from s[] via shfl remap)
        const int base = lane & 28;
        const int lA = base + (q4 >> 1), lB = lA + 2;
        const bool odd = (q4 & 1);
#pragma unroll
        for (int ks = 0; ks < 8; ks++) {
            float x0 = __shfl_sync(0xffffffffu, s[ks][0], lA);
            float y0 = __shfl_sync(0xffffffffu, s[ks][1], lA);
            float x2 = __shfl_sync(0xffffffffu, s[ks][0], lB);
            float y2 = __shfl_sync(0xffffffffu, s[ks][1], lB);
            float x1 = __shfl_sync(0xffffffffu, s[ks][2], lA);
            float y1 = __shfl_sync(0xffffffffu, s[ks][3], lA);
            float x3 = __shfl_sync(0xffffffffu, s[ks][2], lB);
            float y3 = __shfl_sync(0xffffffffu, s[ks][3], lB);
            float a0 = odd ? y0 : x0;
            float a1 = odd ? y1 : x1;
            float a2 = odd ? y2 : x2;
            float a3 = odd ? y3 : x3;
#pragma unroll
            for (int dt = 0; dt < 8; dt++) {
                int vb = (ks*8 + q4)*SK + dt*8 + g;
                mma8(o[dt], a0, a1, a2, a3,
                     to_tf32(Vs[vb]), to_tf32(Vs[vb + 4*SK]));
            }
        }
        __syncthreads();
        buf ^= 1;
    }

    // finalize
    l0 += __shfl_xor_sync(0xffffffffu, l0, 1);
    l0 += __shfl_xor_sync(0xffffffffu, l0, 2);
    l1 += __shfl_xor_sync(0xffffffffu, l1, 1);
    l1 += __shfl_xor_sync(0xffffffffu, l1, 2);
    float i0 = 1.f / l0, i1 = 1.f / l1;

    float* Ob = g_O + ((size_t)b*SEQ + r0)*EMB + h*HD;
#pragma unroll
    for (int dt = 0; dt < 8; dt++) {
        int c = dt*8 + q4*2;
        *(float2*)(Ob + c)         = make_float2(o[dt][0]*i0, o[dt][1]*i0);
        *(float2*)(Ob + 8*EMB + c) = make_float2(o[dt][2]*i1, o[dt][3]*i1);
    }
}

// ---------------------------------------------------------------------------
extern "C" void kernel_launch(void* const* d_in, const int* in_sizes, int n_in,
                              void* d_out, int out_size)
{
    const float* x  = (const float*)d_in[0];
    const float* Wq = (const float*)d_in[1];
    const float* Wk = (const float*)d_in[2];
    const float* Wv = (const float*)d_in[3];
    const float* Wo = (const float*)d_in[4];
    const float* bo = (const float*)d_in[5];
    float* out = (float*)d_out;

    const int gemm_smem = GEMM_SMEM;                               // 73728 B
    const int attn_smem = (128*SK + 4*64*SK) * sizeof(float);      // 104448 B
    cudaFuncSetAttribute(qkv_gemm, cudaFuncAttributeMaxDynamicSharedMemorySize, gemm_smem);
    cudaFuncSetAttribute(proj_gemm, cudaFuncAttributeMaxDynamicSharedMemorySize, gemm_smem);
    cudaFuncSetAttribute(attn_kernel, cudaFuncAttributeMaxDynamicSharedMemorySize, attn_smem);

    qkv_gemm<<<dim3(EMB/128, (BATCH*SEQ)/128, 3), 256, gemm_smem>>>(x, Wq, Wk, Wv);
    attn_kernel<<<dim3(SEQ/128, NH, BATCH), 256, attn_smem>>>();
    proj_gemm<<<dim3(EMB/128, (BATCH*SEQ)/128), 256, gemm_smem>>>(Wo, bo, out);
}

// round 15
// speedup vs baseline: 11.9359x; 1.0312x over previous
#include <cuda_runtime.h>
#include <cstdint>

#define SEQ  2048
#define EMB  1024
#define NH   16
#define HD   64
#define BATCH 4

// Scratch (no cudaMalloc allowed)
__device__ float g_Q[BATCH*NH*SEQ*HD];
__device__ float g_K[BATCH*NH*SEQ*HD];
__device__ float g_V[BATCH*NH*SEQ*HD];
__device__ float g_O[BATCH*SEQ*EMB];
// tf32-pre-rounded copies of inputs
__device__ float g_X [BATCH*SEQ*EMB];
__device__ float g_Wq[EMB*EMB];
__device__ float g_Wk[EMB*EMB];
__device__ float g_Wv[EMB*EMB];
__device__ float g_Wo[EMB*EMB];

__device__ __forceinline__ float to_tf32(float x) {
    float r; asm("cvt.rna.tf32.f32 %0, %1;" : "=f"(r) : "f"(x)); return r;
}

__device__ __forceinline__ void cp16(float* smem_dst, const float* gmem_src) {
    uint32_t s = (uint32_t)__cvta_generic_to_shared(smem_dst);
    asm volatile("cp.async.cg.shared.global [%0], [%1], 16;" :: "r"(s), "l"(gmem_src));
}
__device__ __forceinline__ void cp_commit() {
    asm volatile("cp.async.commit_group;");
}
template<int N>
__device__ __forceinline__ void cp_wait() {
    asm volatile("cp.async.wait_group %0;" :: "n"(N));
}

// D += A(16x8,row) * B(8x8,col)  tf32
__device__ __forceinline__ void mma8(float* d, float a0, float a1, float a2, float a3,
                                     float b0, float b1) {
    uint32_t A0=__float_as_uint(a0), A1=__float_as_uint(a1),
             A2=__float_as_uint(a2), A3=__float_as_uint(a3);
    uint32_t B0=__float_as_uint(b0), B1=__float_as_uint(b1);
    asm volatile("mma.sync.aligned.m16n8k8.row.col.f32.tf32.tf32.f32 "
                 "{%0,%1,%2,%3},{%4,%5,%6,%7},{%8,%9},{%0,%1,%2,%3};"
                 : "+f"(d[0]), "+f"(d[1]), "+f"(d[2]), "+f"(d[3])
                 : "r"(A0), "r"(A1), "r"(A2), "r"(A3), "r"(B0), "r"(B1));
}

// Pre-round a tensor to tf32 (idempotent; applied once so mainloops skip cvt)
__global__ __launch_bounds__(256)
void round_tf32_kernel(const float* __restrict__ src, float* __restrict__ dst, int n4)
{
    int i = blockIdx.x*blockDim.x + threadIdx.x;
    if (i < n4) {
        float4 v = ((const float4*)src)[i];
        v.x = to_tf32(v.x); v.y = to_tf32(v.y);
        v.z = to_tf32(v.z); v.w = to_tf32(v.w);
        ((float4*)dst)[i] = v;
    }
}

#define SA 36   // smem row stride (floats): 36 % 32 = 4 -> conflict-free frag loads
#define GEMM_STAGE (2*128*SA)            // A + B per stage (floats)
#define GEMM_SMEM  (2*GEMM_STAGE*4)      // bytes, 2 stages

// ---------------------------------------------------------------------------
// NT GEMM: C[128x128] = A[128xK]*B[128xK]^T, tf32 mma, cp.async double-
// buffered, inputs pre-rounded to tf32 (NO cvt in mainloop), loop unrolled x2
// so both stage bases are compile-time-static.
// 256 threads = 8 warps (2 M x 4 N), warp tile 64x32, BK = 32.
// ---------------------------------------------------------------------------
__device__ __forceinline__ void gemm_issue(const float* __restrict__ A,
                                           const float* __restrict__ B,
                                           float* stage, int bm0, int bn0, int k0) {
    const int t = threadIdx.x;
    const int lrow = t >> 3, lc4 = t & 7;
    float* As = stage;
    float* Bs = stage + 128*SA;
#pragma unroll
    for (int u = 0; u < 4; u++) {
        int row = u*32 + lrow;
        cp16(As + row*SA + lc4*4, A + (size_t)(bm0+row)*EMB + k0 + lc4*4);
        cp16(Bs + row*SA + lc4*4, B + (size_t)(bn0+row)*EMB + k0 + lc4*4);
    }
}

__device__ __forceinline__ void gemm_compute(const float* __restrict__ As,
                                             const float* __restrict__ Bs,
                                             int wm, int wn, int g, int q4,
                                             float acc[4][4][4]) {
#pragma unroll
    for (int ks = 0; ks < 4; ks++) {
        float af[4][4], bf[4][2];
#pragma unroll
        for (int mt = 0; mt < 4; mt++) {
            int r = wm + mt*16 + g;
            af[mt][0] = As[r*SA     + ks*8 + q4];
            af[mt][1] = As[(r+8)*SA + ks*8 + q4];
            af[mt][2] = As[r*SA     + ks*8 + q4 + 4];
            af[mt][3] = As[(r+8)*SA + ks*8 + q4 + 4];
        }
#pragma unroll
        for (int nt = 0; nt < 4; nt++) {
            int c = wn + nt*8 + g;
            bf[nt][0] = Bs[c*SA + ks*8 + q4];
            bf[nt][1] = Bs[c*SA + ks*8 + q4 + 4];
        }
#pragma unroll
        for (int mt = 0; mt < 4; mt++)
#pragma unroll
            for (int nt = 0; nt < 4; nt++)
                mma8(acc[mt][nt], af[mt][0], af[mt][1], af[mt][2], af[mt][3],
                     bf[nt][0], bf[nt][1]);
    }
}

__device__ __forceinline__ void gemm_mainloop(const float* __restrict__ A,
                                              const float* __restrict__ B,
                                              float* sm, int bm0, int bn0,
                                              float acc[4][4][4]) {
    const int t = threadIdx.x;
    const int warp = t >> 5, lane = t & 31, g = lane >> 2, q4 = lane & 3;
    const int wm = (warp & 1) * 64, wn = (warp >> 1) * 32;
    float* st0 = sm;
    float* st1 = sm + GEMM_STAGE;

    gemm_issue(A, B, st0, bm0, bn0, 0);
    cp_commit();

#pragma unroll 1
    for (int k0 = 0; k0 < EMB; k0 += 64) {
        // k0+32 is always < EMB here (k0 max = EMB-64)
        gemm_issue(A, B, st1, bm0, bn0, k0 + 32);
        cp_commit();
        cp_wait<1>();
        __syncthreads();
        gemm_compute(st0, st0 + 128*SA, wm, wn, g, q4, acc);
        __syncthreads();

        if (k0 + 64 < EMB) {
            gemm_issue(A, B, st0, bm0, bn0, k0 + 64);
            cp_commit();
            cp_wait<1>();
        } else {
            cp_wait<0>();
        }
        __syncthreads();
        gemm_compute(st1, st1 + 128*SA, wm, wn, g, q4, acc);
        __syncthreads();
    }
}

// QKV projection: reads pre-rounded g_X / g_W*, writes tf32-rounded [B,H,S,HD]
__global__ __launch_bounds__(256, 2)
void qkv_gemm()
{
    extern __shared__ float sm[];
    const float* W = (blockIdx.z == 0) ? g_Wq : (blockIdx.z == 1) ? g_Wk : g_Wv;
    float* Out     = (blockIdx.z == 0) ? g_Q  : (blockIdx.z == 1) ? g_K  : g_V;

    const int bm0 = blockIdx.y*128, bn0 = blockIdx.x*128;
    float acc[4][4][4] = {};
    gemm_mainloop(g_X, W, sm, bm0, bn0, acc);

    const int t = threadIdx.x;
    const int warp = t >> 5, lane = t & 31, g = lane >> 2, q4 = lane & 3;
    const int wm = (warp & 1) * 64, wn = (warp >> 1) * 32;
#pragma unroll
    for (int mt = 0; mt < 4; mt++) {
        int m = bm0 + wm + mt*16 + g;
        int bb = m >> 11, s = m & 2047;
#pragma unroll
        for (int nt = 0; nt < 4; nt++) {
            int n = bn0 + wn + nt*8 + q4*2;
            int h = n >> 6, d = n & 63;
            float* base = Out + (((size_t)(bb*NH + h)*SEQ + s)*HD + d);
            *(float2*)base = make_float2(to_tf32(acc[mt][nt][0]), to_tf32(acc[mt][nt][1]));
            *(float2*)(base + 8*HD) = make_float2(to_tf32(acc[mt][nt][2]), to_tf32(acc[mt][nt][3]));
        }
    }
}

// Output projection: out = g_O @ g_Wo^T + bo (g_O, g_Wo pre-rounded)
__global__ __launch_bounds__(256, 2)
void proj_gemm(const float* __restrict__ bo, float* __restrict__ outp)
{
    extern __shared__ float sm[];
    const int bm0 = blockIdx.y*128, bn0 = blockIdx.x*128;
    float acc[4][4][4] = {};
    gemm_mainloop(g_O, g_Wo, sm, bm0, bn0, acc);

    const int t = threadIdx.x;
    const int warp = t >> 5, lane = t & 31, g = lane >> 2, q4 = lane & 3;
    const int wm = (warp & 1) * 64, wn = (warp >> 1) * 32;
#pragma unroll
    for (int mt = 0; mt < 4; mt++) {
        int m = bm0 + wm + mt*16 + g;
#pragma unroll
        for (int nt = 0; nt < 4; nt++) {
            int n = bn0 + wn + nt*8 + q4*2;
            float2 bv = *(const float2*)(bo + n);
            *(float2*)(outp + (size_t)m*EMB + n) =
                make_float2(acc[mt][nt][0] + bv.x, acc[mt][nt][1] + bv.y);
            *(float2*)(outp + (size_t)(m+8)*EMB + n) =
                make_float2(acc[mt][nt][2] + bv.x, acc[mt][nt][3] + bv.y);
        }
    }
}

// ---------------------------------------------------------------------------
// Causal flash attention, tf32 mma, cp.async double-buffered K/V.
// Q/K/V are pre-rounded tf32 -> no cvt on fragment loads (only P after exp).
// Q scale 0.125 is a power of two: exact in tf32, no re-round.
// Block = 128 q-rows of one (b,h). 8 warps, each owns 16 q-rows.
// ---------------------------------------------------------------------------
#define SK 68   // smem row stride for attn tiles
#define KV_STAGE (64*SK)

__global__ __launch_bounds__(256, 2)
void attn_kernel()
{
    extern __shared__ float sm[];
    float* Qs  = sm;                      // 128*SK
    float* Ksb = sm + 128*SK;             // 2 stages of 64*SK
    float* Vsb = Ksb + 2*KV_STAGE;        // 2 stages of 64*SK

    const int t = threadIdx.x;
    const int warp = t >> 5, lane = t & 31, g = lane >> 2, q4 = lane & 3;
    const int qt = (int)gridDim.x - 1 - (int)blockIdx.x;   // big tiles first
    const int h = blockIdx.y, b = blockIdx.z;

    const float* Qg = g_Q + ((size_t)(b*NH + h)*SEQ + qt*128)*HD;
    const float* Kg = g_K + ((size_t)(b*NH + h)*SEQ)*HD;
    const float* Vg = g_V + ((size_t)(b*NH + h)*SEQ)*HD;

    const int lrow = t >> 4, lc4 = t & 15;   // loader for 64x64 tiles

    // Issue kb=0 K/V loads
#pragma unroll
    for (int u = 0; u < 4; u++) {
        int row = u*16 + lrow;
        cp16(Ksb + row*SK + lc4*4, Kg + (size_t)row*HD + lc4*4);
        cp16(Vsb + row*SK + lc4*4, Vg + (size_t)row*HD + lc4*4);
    }
    cp_commit();

    // Load Q tile, fold softmax scale 1/8 (exact in tf32)
#pragma unroll
    for (int u = 0; u < 8; u++) {
        int idx = u*256 + t;
        int row = idx >> 4, c4 = idx & 15;
        float4 v = ((const float4*)Qg)[idx];
        v.x *= 0.125f; v.y *= 0.125f; v.z *= 0.125f; v.w *= 0.125f;
        *(float4*)(Qs + row*SK + c4*4) = v;
    }

    float o[8][4] = {};
    float m0 = -1e30f, m1 = -1e30f, l0 = 0.f, l1 = 0.f;
    const int r0 = qt*128 + warp*16 + g;         // global q row (and r0+8)

    const int kbmax = 2*qt + 1;
    int buf = 0;
    for (int kb = 0; kb <= kbmax; kb++) {
        const bool more = (kb < kbmax);
        if (more) {
            float* Kn = Ksb + (buf^1)*KV_STAGE;
            float* Vn = Vsb + (buf^1)*KV_STAGE;
            const float* Kgn = Kg + (size_t)(kb+1)*64*HD;
            const float* Vgn = Vg + (size_t)(kb+1)*64*HD;
#pragma unroll
            for (int u = 0; u < 4; u++) {
                int row = u*16 + lrow;
                cp16(Kn + row*SK + lc4*4, Kgn + (size_t)row*HD + lc4*4);
                cp16(Vn + row*SK + lc4*4, Vgn + (size_t)row*HD + lc4*4);
            }
            cp_commit();
            cp_wait<1>();
        } else {
            cp_wait<0>();
        }
        __syncthreads();

        const float* Ks = Ksb + buf*KV_STAGE;
        const float* Vs = Vsb + buf*KV_STAGE;

        // S = Q * K^T (scaled)
        float s[8][4] = {};
#pragma unroll
        for (int ks = 0; ks < 8; ks++) {
            int r = (warp*16 + g)*SK + ks*8 + q4;
            float a0 = Qs[r];
            float a1 = Qs[r + 8*SK];
            float a2 = Qs[r + 4];
            float a3 = Qs[r + 8*SK + 4];
#pragma unroll
            for (int nt = 0; nt < 8; nt++) {
                int c = (nt*8 + g)*SK + ks*8 + q4;
                mma8(s[nt], a0, a1, a2, a3, Ks[c], Ks[c+4]);
            }
        }

        // causal mask + row max
        const int cb = kb*64 + q4*2;
        float mt0 = -1e30f, mt1 = -1e30f;
#pragma unroll
        for (int nt = 0; nt < 8; nt++) {
            int c0 = cb + nt*8, c1 = c0 + 1;
            if (c0 > r0)     s[nt][0] = -1e30f;
            if (c1 > r0)     s[nt][1] = -1e30f;
            if (c0 > r0 + 8) s[nt][2] = -1e30f;
            if (c1 > r0 + 8) s[nt][3] = -1e30f;
            mt0 = fmaxf(mt0, fmaxf(s[nt][0], s[nt][1]));
            mt1 = fmaxf(mt1, fmaxf(s[nt][2], s[nt][3]));
        }
        mt0 = fmaxf(mt0, __shfl_xor_sync(0xffffffffu, mt0, 1));
        mt0 = fmaxf(mt0, __shfl_xor_sync(0xffffffffu, mt0, 2));
        mt1 = fmaxf(mt1, __shfl_xor_sync(0xffffffffu, mt1, 1));
        mt1 = fmaxf(mt1, __shfl_xor_sync(0xffffffffu, mt1, 2));

        float mn0 = fmaxf(m0, mt0), mn1 = fmaxf(m1, mt1);
        float cr0 = __expf(m0 - mn0), cr1 = __expf(m1 - mn1);
        m0 = mn0; m1 = mn1;
        l0 *= cr0; l1 *= cr1;
#pragma unroll
        for (int dt = 0; dt < 8; dt++) {
            o[dt][0] *= cr0; o[dt][1] *= cr0;
            o[dt][2] *= cr1; o[dt][3] *= cr1;
        }
        // P = exp(S - m), accumulate l, convert to tf32 in place
#pragma unroll
        for (int nt = 0; nt < 8; nt++) {
            s[nt][0] = __expf(s[nt][0] - m0);
            s[nt][1] = __expf(s[nt][1] - m0);
            s[nt][2] = __expf(s[nt][2] - m1);
            s[nt][3] = __expf(s[nt][3] - m1);
            l0 += s[nt][0] + s[nt][1];
            l1 += s[nt][2] + s[nt][3];
            s[nt][0] = to_tf32(s[nt][0]); s[nt][1] = to_tf32(s[nt][1]);
            s[nt][2] = to_tf32(s[nt][2]); s[nt][3] = to_tf32(s[nt][3]);
        }

        // O += P * V  (A fragments built from s[] via shfl remap)
        const int base = lane & 28;
        const int lA = base + (q4 >> 1), lB = lA + 2;
        const bool odd = (q4 & 1);
#pragma unroll
        for (int ks = 0; ks < 8; ks++) {
            float x0 = __shfl_sync(0xffffffffu, s[ks][0], lA);
            float y0 = __shfl_sync(0xffffffffu, s[ks][1], lA);
            float x2 = __shfl_sync(0xffffffffu, s[ks][0], lB);
            float y2 = __shfl_sync(0xffffffffu, s[ks][1], lB);
            float x1 = __shfl_sync(0xffffffffu, s[ks][2], lA);
            float y1 = __shfl_sync(0xffffffffu, s[ks][3], lA);
            float x3 = __shfl_sync(0xffffffffu, s[ks][2], lB);
            float y3 = __shfl_sync(0xffffffffu, s[ks][3], lB);
            float a0 = odd ? y0 : x0;
            float a1 = odd ? y1 : x1;
            float a2 = odd ? y2 : x2;
            float a3 = odd ? y3 : x3;
#pragma unroll
            for (int dt = 0; dt < 8; dt++) {
                int vb = (ks*8 + q4)*SK + dt*8 + g;
                mma8(o[dt], a0, a1, a2, a3, Vs[vb], Vs[vb + 4*SK]);
            }
        }
        __syncthreads();
        buf ^= 1;
    }

    // finalize
    l0 += __shfl_xor_sync(0xffffffffu, l0, 1);
    l0 += __shfl_xor_sync(0xffffffffu, l0, 2);
    l1 += __shfl_xor_sync(0xffffffffu, l1, 1);
    l1 += __shfl_xor_sync(0xffffffffu, l1, 2);
    float i0 = 1.f / l0, i1 = 1.f / l1;

    // store tf32-rounded (feeds proj's mma; same rounding proj would apply)
    float* Ob = g_O + ((size_t)b*SEQ + r0)*EMB + h*HD;
#pragma unroll
    for (int dt = 0; dt < 8; dt++) {
        int c = dt*8 + q4*2;
        *(float2*)(Ob + c) = make_float2(to_tf32(o[dt][0]*i0), to_tf32(o[dt][1]*i0));
        *(float2*)(Ob + 8*EMB + c) = make_float2(to_tf32(o[dt][2]*i1), to_tf32(o[dt][3]*i1));
    }
}

// ---------------------------------------------------------------------------
extern "C" void kernel_launch(void* const* d_in, const int* in_sizes, int n_in,
                              void* d_out, int out_size)
{
    const float* x  = (const float*)d_in[0];
    const float* Wq = (const float*)d_in[1];
    const float* Wk = (const float*)d_in[2];
    const float* Wv = (const float*)d_in[3];
    const float* Wo = (const float*)d_in[4];
    const float* bo = (const float*)d_in[5];
    float* out = (float*)d_out;

    float *dX, *dWq, *dWk, *dWv, *dWo;
    cudaGetSymbolAddress((void**)&dX,  g_X);
    cudaGetSymbolAddress((void**)&dWq, g_Wq);
    cudaGetSymbolAddress((void**)&dWk, g_Wk);
    cudaGetSymbolAddress((void**)&dWv, g_Wv);
    cudaGetSymbolAddress((void**)&dWo, g_Wo);

    const int gemm_smem = GEMM_SMEM;                               // 73728 B
    const int attn_smem = (128*SK + 4*64*SK) * sizeof(float);      // 104448 B
    cudaFuncSetAttribute(qkv_gemm, cudaFuncAttributeMaxDynamicSharedMemorySize, gemm_smem);
    cudaFuncSetAttribute(proj_gemm, cudaFuncAttributeMaxDynamicSharedMemorySize, gemm_smem);
    cudaFuncSetAttribute(attn_kernel, cudaFuncAttributeMaxDynamicSharedMemorySize, attn_smem);

    const int NX4 = BATCH*SEQ*EMB/4, NW4 = EMB*EMB/4;
    round_tf32_kernel<<<(NX4+255)/256, 256>>>(x,  dX,  NX4);
    round_tf32_kernel<<<(NW4+255)/256, 256>>>(Wq, dWq, NW4);
    round_tf32_kernel<<<(NW4+255)/256, 256>>>(Wk, dWk, NW4);
    round_tf32_kernel<<<(NW4+255)/256, 256>>>(Wv, dWv, NW4);
    round_tf32_kernel<<<(NW4+255)/256, 256>>>(Wo, dWo, NW4);

    qkv_gemm<<<dim3(EMB/128, (BATCH*SEQ)/128, 3), 256, gemm_smem>>>();
    attn_kernel<<<dim3(SEQ/128, NH, BATCH), 256, attn_smem>>>();
    proj_gemm<<<dim3(EMB/128, (BATCH*SEQ)/128), 256, gemm_smem>>>(bo, out);
}